// round 16
// baseline (speedup 1.0000x reference)
#include <cuda_runtime.h>
#include <math.h>

#define TMAX 256
#define LOG2PI 1.8378770664093453
#define SEGA 8
#define GRP 8
#define SEG 16

// ---------------- device scratch ----------------
__device__ float g_pA[TMAX][256], g_pC[TMAX][256], g_pJ[TMAX][256];
__device__ float g_pb[TMAX][16], g_pe[TMAX][16];
__device__ float g_lA[32][256], g_lC[32][256], g_lJ[32][256];
__device__ float g_lb[32][16], g_le[32][16];
__device__ float g_gA[4][256], g_gC[4][256], g_gJ[4][256];
__device__ float g_gb[4][16], g_ge[4][16];
__device__ float g_xC[4][256], g_xb[4][16];
__device__ float g_P[TMAX][256], g_ba[TMAX][16];
__device__ float g_bcov[TMAX][256], g_Q[TMAX][256];
__device__ float g_mP[TMAX][256], g_mQ[TMAX][256], g_mQo[TMAX][256];
__device__ float g_Gx[16][256], g_Gox[16][256];
__device__ float g_ldp[TMAX], g_lds[TMAX];
__device__ double g_accT[TMAX];
__device__ float g_Lr[TMAX][256], g_Lu[TMAX][16];
__device__ float g_Sr[32][256], g_Su[32][16];
__device__ float g_Gr[32][256], g_Gu[32][16];
__device__ float g_OmP[256], g_om[256], g_Om0[256], g_Em[256], g_Fm[256];
__device__ float g_Ac[256], g_Cc[256], g_Jc[256], g_Kc[256], g_Ec[256];
__device__ float g_cb0[16], g_e0v[16];
__device__ float g_fcF[256], g_fmF[16];
__device__ double g_sc[8];
__device__ unsigned int g_ctr[4];

__device__ __forceinline__ float dot_rc(const float* A, const float* B, int i, int j) {
    float s = 0.f;
#pragma unroll
    for (int k = 0; k < 16; k++) s = fmaf(A[i * 16 + k], B[k * 16 + j], s);
    return s;
}
__device__ __forceinline__ float dot_tc(const float* A, const float* B, int i, int j) {
    float s = 0.f;
#pragma unroll
    for (int k = 0; k < 16; k++) s = fmaf(A[k * 16 + i], B[k * 16 + j], s);
    return s;
}
__device__ __forceinline__ float dot_rt(const float* A, const float* B, int i, int j) {
    float s = 0.f;
#pragma unroll
    for (int k = 0; k < 16; k++) s = fmaf(A[i * 16 + k], B[j * 16 + k], s);
    return s;
}
__device__ __forceinline__ float mv(const float* M, const float* v, int r) {
    float s = 0.f;
#pragma unroll
    for (int k = 0; k < 16; k++) s = fmaf(M[r * 16 + k], v[k], s);
    return s;
}

// Warp GJ solve A X = B (16 RHS); writes X^T to Xt; returns sum(log|piv|).
__device__ __forceinline__ float warp_gj_solve(const float* Am, const float* Bm,
                                               float* Xt, int lane) {
    float a[16];
    const float* src = (lane < 16) ? (Am + lane) : (Bm + lane - 16);
#pragma unroll
    for (int r = 0; r < 16; r++) a[r] = src[r * 16];
    float mypiv = 1.f;
#pragma unroll
    for (int p = 0; p < 16; p++) {
        float f[16];
#pragma unroll
        for (int r = 0; r < 16; r++) f[r] = __shfl_sync(0xffffffffu, a[r], p);
        float x = f[p];
        if (lane == p) mypiv = x;
        float r0;
        asm("rcp.approx.f32 %0, %1;" : "=f"(r0) : "f"(x));
        float pivinv = r0 * (2.0f - x * r0);
        a[p] *= pivinv;
#pragma unroll
        for (int r = 0; r < 16; r++)
            if (r != p) a[r] = fmaf(-f[r], a[p], a[r]);
    }
    float lg = __logf(fabsf(mypiv));
#pragma unroll
    for (int o = 16; o; o >>= 1) lg += __shfl_xor_sync(0xffffffffu, lg, o);
    if (lane >= 16) {
        float4* dst = reinterpret_cast<float4*>(Xt + (lane - 16) * 16);
        dst[0] = make_float4(a[0], a[1], a[2], a[3]);
        dst[1] = make_float4(a[4], a[5], a[6], a[7]);
        dst[2] = make_float4(a[8], a[9], a[10], a[11]);
        dst[3] = make_float4(a[12], a[13], a[14], a[15]);
    }
    return lg;
}

// Warp GJ vector solve A x = b; writes x to xout (lane 16 stores).
__device__ __forceinline__ void warp_gj_vecsolve(const float* Am, const float* bv,
                                                 float* xout, int lane) {
    float a[16];
    if (lane < 16) {
#pragma unroll
        for (int r = 0; r < 16; r++) a[r] = Am[r * 16 + lane];
    } else {
#pragma unroll
        for (int r = 0; r < 16; r++) a[r] = bv[r];
    }
#pragma unroll
    for (int p = 0; p < 16; p++) {
        float f[16];
#pragma unroll
        for (int r = 0; r < 16; r++) f[r] = __shfl_sync(0xffffffffu, a[r], p);
        float x = f[p];
        float r0;
        asm("rcp.approx.f32 %0, %1;" : "=f"(r0) : "f"(x));
        float pivinv = r0 * (2.0f - x * r0);
        a[p] *= pivinv;
#pragma unroll
        for (int r = 0; r < 16; r++)
            if (r != p) a[r] = fmaf(-f[r], a[p], a[r]);
    }
    if (lane == 16) {
        float4* dst = reinterpret_cast<float4*>(xout);
        dst[0] = make_float4(a[0], a[1], a[2], a[3]);
        dst[1] = make_float4(a[4], a[5], a[6], a[7]);
        dst[2] = make_float4(a[8], a[9], a[10], a[11]);
        dst[3] = make_float4(a[12], a[13], a[14], a[15]);
    }
}

// Full element compose (multi-RHS GJ): prefix ∘ next -> prefix.
__device__ __forceinline__ void compose_full(
    float* PA, float* PC, float* PJ, float* Pb, float* Pe,
    const float* NA, const float* NC, const float* NJ, const float* Nb, const float* Ne,
    float* IpW, float* ZAt, float* ZCt, float* JA,
    float* w1, float* vJ, float* zb, const float* Id,
    int tid, int i, int j, int lane, int wid) {
    IpW[tid] = Id[tid] + dot_rc(PC, NJ, i, j);
    if (tid < 16) w1[tid] = Pb[tid] + mv(PC, Ne, tid);
    else if (tid < 32) vJ[tid - 16] = mv(NJ, Pb, tid - 16);
    __syncthreads();
    if (wid == 0) {
        warp_gj_solve(IpW, PA, ZAt, lane);
    } else if (wid == 5) {
        warp_gj_solve(IpW, PC, ZCt, lane);
    } else if (wid == 2) {
        warp_gj_vecsolve(IpW, w1, zb, lane);
    } else if (wid != 4) {
        const int h = (wid == 1) ? (tid - 32) : (wid == 3) ? (tid - 64) : (tid - 128);
        JA[h] = dot_rc(NJ, PA, h >> 4, h & 15);
        JA[h + 128] = dot_rc(NJ, PA, (h + 128) >> 4, (h + 128) & 15);
    }
    __syncthreads();
    {
        float na = dot_rt(NA, ZAt, i, j);
        float cw = dot_rt(NA, ZCt, i, j);
        float nj = dot_rc(ZAt, JA, i, j) + PJ[tid];
        float nb = 0.f, ne = 0.f;
        if (tid < 16) {
            nb = mv(NA, zb, tid) + Nb[tid];
#pragma unroll
            for (int k = 0; k < 16; k++) ne = fmaf(ZAt[tid * 16 + k], Ne[k] - vJ[k], ne);
            ne += Pe[tid];
        }
        PA[tid] = na;
        PJ[tid] = nj;
        ZCt[tid] = cw;
        if (tid < 16) { Pb[tid] = nb; Pe[tid] = ne; }
    }
    __syncthreads();
    PC[tid] = dot_rt(ZCt, NA, i, j) + NC[tid];
    __syncthreads();
}

// Light (b,C) compose: state (Cst,bst) ∘ element (global) -> state.
__device__ __forceinline__ void light_compose(
    float* Cst, float* bst,
    const float* gA, const float* gC, const float* gJ,
    const float* gb, const float* ge,
    float* NA, float* NJ, float* IpW, float* ZCt, float* zb,
    float* Nb2, float* w1, const float* Id,
    int tid, int i, int j, int lane, int wid) {
    NA[tid] = gA[tid]; NJ[tid] = gJ[tid];
    if (tid < 16) Nb2[tid] = gb[tid];
    else if (tid < 32) w1[tid - 16] = ge[tid - 16];
    __syncthreads();
    IpW[tid] = Id[tid] + dot_rc(Cst, NJ, i, j);
    if (tid < 16) {
        float s = bst[tid];
#pragma unroll
        for (int k = 0; k < 16; k++) s = fmaf(Cst[tid * 16 + k], w1[k], s);
        zb[tid] = s;
    }
    __syncthreads();
    if (wid == 0) warp_gj_solve(IpW, Cst, ZCt, lane);
    else if (wid == 2) warp_gj_vecsolve(IpW, zb, w1, lane);
    __syncthreads();
    {
        float cw = dot_rt(NA, ZCt, i, j);
        float nb = 0.f;
        if (tid < 16) nb = mv(NA, w1, tid) + Nb2[tid];
        ZCt[tid] = cw;
        if (tid < 16) bst[tid] = nb;
    }
    __syncthreads();
    Cst[tid] = dot_rt(ZCt, NA, i, j) + gC[tid];
    __syncthreads();
}

// ================= setup =================
__global__ void __launch_bounds__(256, 1) k_setup(
    const float* obs, const float* ppm_, const float* ppc, const float* wp,
    const float* pb_, const float* ptc, const float* wep, const float* peb,
    const float* pec, const float* qpm, const float* qpc, const float* wq_,
    const float* qb, const float* qtc, const float* hq_, const float* qeb,
    const float* qec, int Tn) {
    __shared__ float Wq[256], Sq[256], Hq[256], Rq[256], Wp[256], Wep[256], Id[256];
    __shared__ float MI[6][256], VI[6][256];
    __shared__ float Hpc[256], U1[256], V[256], S[256], Sc[256];
    __shared__ float Km[256], Kc[256], Ec[256], IKH[256], B1[256], t3[256];
    __shared__ float ldsh[8];
    __shared__ float bq[16], dq[16], pm0[16], innov[16], y0[16], c2v[16];
    const int tid = threadIdx.x, i = tid >> 4, j = tid & 15;
    const int lane = tid & 31, wid = tid >> 5;
    if (tid < 4) g_ctr[tid] = 0;  // reset last-block counters each replay
    Wq[tid] = wq_[tid]; Sq[tid] = qtc[tid]; Hq[tid] = hq_[tid]; Rq[tid] = qec[tid];
    Wp[tid] = wp[tid]; Wep[tid] = wep[tid]; Id[tid] = (i == j) ? 1.f : 0.f;
    MI[0][tid] = ptc[tid]; MI[1][tid] = pec[tid]; MI[2][tid] = ppc[tid];
    MI[3][tid] = qtc[tid]; MI[4][tid] = qec[tid]; MI[5][tid] = qpc[tid];
    if (tid < 16) { bq[tid] = qb[tid]; dq[tid] = qeb[tid]; pm0[tid] = qpm[tid]; y0[tid] = obs[tid]; }
    __syncthreads();
    if (wid < 6) {
        float ld = warp_gj_solve(MI[wid], Id, VI[wid], lane);
        if (lane == 0) ldsh[wid] = ld;
    }
    __syncthreads();
    g_OmP[tid] = -0.5f * VI[0][tid];
    g_om[tid] = -0.5f * VI[1][tid];
    g_Om0[tid] = -0.5f * VI[2][tid];
    B1[tid] = dot_rc(VI[0], Wp, i, j);
    t3[tid] = -0.5f * dot_rc(VI[1], Wep, i, j);
    Hpc[tid] = dot_rc(Hq, MI[5], i, j);
    U1[tid] = dot_rc(Hq, Sq, i, j);
    V[tid] = dot_rc(Hq, Wq, i, j);
    if (tid < 16) innov[tid] = y0[tid] - mv(Hq, pm0, tid) - dq[tid];
    __syncthreads();
    g_Fm[tid] = dot_tc(Wp, B1, i, j);
    g_Em[tid] = dot_tc(Wep, t3, i, j);
    S[tid] = dot_rt(Hpc, Hq, i, j) + Rq[tid];
    Sc[tid] = dot_rt(U1, Hq, i, j) + Rq[tid];
    __syncthreads();
    if (wid == 0) {
        float ld = warp_gj_solve(S, Hpc, Km, lane);
        if (lane == 0) ldsh[6] = ld;
    } else if (wid == 2) {
        warp_gj_solve(Sc, U1, Kc, lane);
    } else if (wid == 5) {
        warp_gj_solve(Sc, V, Ec, lane);
    }
    __syncthreads();
    g_pA[0][tid] = 0.f; g_pJ[0][tid] = 0.f;
    g_pC[0][tid] = MI[5][tid] - dot_rc(Km, Hpc, i, j);
    IKH[tid] = Id[tid] - dot_rc(Kc, Hq, i, j);
    if (tid < 16) {
        c2v[tid] = mv(Hq, bq, tid) + dq[tid];
        g_pb[0][tid] = pm0[tid] + mv(Km, innov, tid);
        g_pe[0][tid] = 0.f;
    }
    __syncthreads();
    g_Ac[tid] = dot_rc(IKH, Wq, i, j);
    g_Cc[tid] = dot_rc(IKH, Sq, i, j);
    g_Jc[tid] = dot_rc(Ec, V, i, j);
    g_Kc[tid] = Kc[tid]; g_Ec[tid] = Ec[tid];
    if (tid < 16) {
        g_cb0[tid] = mv(IKH, bq, tid) - mv(Kc, dq, tid);
        g_e0v[tid] = mv(Ec, c2v, tid);
    }
    if (tid == 0) {
        double LDp = ldsh[0], LDe = ldsh[1], LDpr = ldsh[2];
        double LDSq = ldsh[3], LDRq = ldsh[4], ldqp = ldsh[5], ldS0 = ldsh[6];
        g_sc[0] = -0.5 * (16.0 * LOG2PI + LDpr) - 0.5 * (16.0 * LOG2PI + LDe);
        g_sc[1] = -8.0 * LOG2PI - 0.5 * LDe - 0.5 * LDp + 8.0;
        g_sc[2] = ldqp + LDRq - ldS0;
        g_sc[3] = LDSq;
        g_sc[4] = LDRq;
    }
}

// ================= elemA =================
__global__ void __launch_bounds__(256, 1) k_elemA(const float* obs, int Tn) {
    __shared__ float Ac[256], Cc[256], Jc[256], Kc[256], Ec[256], Id[256];
    __shared__ float A[256], C[256], J[256];
    __shared__ float IpW[256], ZAt[256], ZCt[256], JA[256];
    __shared__ float cb0[16], e0v[16];
    __shared__ float bv[16], ev[16], bt[16], et[16], w1[16], vJ[16], zb[16], yv[16];
    const int tid = threadIdx.x, i = tid >> 4, j = tid & 15;
    const int lane = tid & 31, wid = tid >> 5;
    const int t0 = blockIdx.x * SEGA;
    if (t0 >= Tn) return;
    const int tend = min(t0 + SEGA, Tn);
    Ac[tid] = g_Ac[tid]; Cc[tid] = g_Cc[tid]; Jc[tid] = g_Jc[tid];
    Kc[tid] = g_Kc[tid]; Ec[tid] = g_Ec[tid]; Id[tid] = (i == j) ? 1.f : 0.f;
    if (tid < 16) { cb0[tid] = g_cb0[tid]; e0v[tid] = g_e0v[tid]; }
    __syncthreads();
    if (t0 == 0) {
        A[tid] = g_pA[0][tid]; C[tid] = g_pC[0][tid]; J[tid] = g_pJ[0][tid];
        if (tid < 16) { bv[tid] = g_pb[0][tid]; ev[tid] = g_pe[0][tid]; }
    } else {
        if (tid < 16) yv[tid] = obs[t0 * 16 + tid];
        __syncthreads();
        A[tid] = Ac[tid]; C[tid] = Cc[tid]; J[tid] = Jc[tid];
        if (tid < 16) { bv[tid] = cb0[tid] + mv(Kc, yv, tid); ev[tid] = mv(Ec, yv, tid) - e0v[tid]; }
        __syncthreads();
        g_pA[t0][tid] = A[tid]; g_pC[t0][tid] = C[tid]; g_pJ[t0][tid] = J[tid];
        if (tid < 16) { g_pb[t0][tid] = bv[tid]; g_pe[t0][tid] = ev[tid]; }
    }
    __syncthreads();
    for (int t = t0 + 1; t < tend; t++) {
        if (tid < 16) yv[tid] = obs[t * 16 + tid];
        __syncthreads();
        if (tid < 16) bt[tid] = cb0[tid] + mv(Kc, yv, tid);
        else if (tid < 32) et[tid - 16] = mv(Ec, yv, tid - 16) - e0v[tid - 16];
        __syncthreads();
        compose_full(A, C, J, bv, ev, Ac, Cc, Jc, bt, et,
                     IpW, ZAt, ZCt, JA, w1, vJ, zb, Id, tid, i, j, lane, wid);
        g_pA[t][tid] = A[tid]; g_pC[t][tid] = C[tid]; g_pJ[t][tid] = J[tid];
        if (tid < 16) { g_pb[t][tid] = bv[tid]; g_pe[t][tid] = ev[tid]; }
        __syncthreads();
    }
}

// ================= elemB: B1 (+ last block does B2 scan) =================
__global__ void __launch_bounds__(256, 1) k_elemB(int Tn) {
    __shared__ float A[256], C[256], J[256], Id[256];
    __shared__ float NA[256], NC[256], NJ[256];
    __shared__ float IpW[256], ZAt[256], ZCt[256], JA[256];
    __shared__ float bv[16], ev[16], Nb[16], Ne[16], w1[16], vJ[16], zb[16];
    __shared__ unsigned isLast;
    const int tid = threadIdx.x, i = tid >> 4, j = tid & 15;
    const int lane = tid & 31, wid = tid >> 5;
    const int nsegA = (Tn + SEGA - 1) / SEGA;
    const int ngrp = (nsegA + GRP - 1) / GRP;
    const int g = blockIdx.x;
    const int k0 = g * GRP;
    Id[tid] = (i == j) ? 1.f : 0.f;
    A[tid] = Id[tid]; C[tid] = 0.f; J[tid] = 0.f;
    if (tid < 16) { bv[tid] = 0.f; ev[tid] = 0.f; }
    __syncthreads();
    if (k0 < nsegA) {
        const int kend = min(k0 + GRP, nsegA);
        for (int k = k0; k < kend; k++) {
            g_lA[k][tid] = A[tid]; g_lC[k][tid] = C[tid]; g_lJ[k][tid] = J[tid];
            if (tid < 16) { g_lb[k][tid] = bv[tid]; g_le[k][tid] = ev[tid]; }
            const int tl = min(k * SEGA + SEGA - 1, Tn - 1);
            NA[tid] = g_pA[tl][tid]; NC[tid] = g_pC[tl][tid]; NJ[tid] = g_pJ[tl][tid];
            if (tid < 16) { Nb[tid] = g_pb[tl][tid]; Ne[tid] = g_pe[tl][tid]; }
            __syncthreads();
            compose_full(A, C, J, bv, ev, NA, NC, NJ, Nb, Ne,
                         IpW, ZAt, ZCt, JA, w1, vJ, zb, Id, tid, i, j, lane, wid);
        }
        g_gA[g][tid] = A[tid]; g_gC[g][tid] = C[tid]; g_gJ[g][tid] = J[tid];
        if (tid < 16) { g_gb[g][tid] = bv[tid]; g_ge[g][tid] = ev[tid]; }
    }
    // last-block: run the (b,C) exclusive scan over group totals
    __threadfence();
    __syncthreads();
    if (tid == 0) isLast = (atomicAdd(&g_ctr[0], 1u) == gridDim.x - 1);
    __syncthreads();
    if (!isLast) return;
    {
        // reuse A as Cst, bv as bst
        A[tid] = 0.f;
        if (tid < 16) bv[tid] = 0.f;
        __syncthreads();
        for (int gg = 0; gg < ngrp; gg++) {
            g_xC[gg][tid] = A[tid];
            if (tid < 16) g_xb[gg][tid] = bv[tid];
            if (gg == ngrp - 1) break;
            __syncthreads();
            light_compose(A, bv, g_gA[gg], g_gC[gg], g_gJ[gg], g_gb[gg], g_ge[gg],
                          NA, NJ, IpW, ZCt, zb, Nb, w1, Id, tid, i, j, lane, wid);
        }
    }
}

// ================= elemCD: 2 light composes + phaseD =================
__global__ void __launch_bounds__(256, 1) k_elemCD(
    const float* wq_, const float* qtc, const float* hq_, const float* qec,
    const float* qb, const float* wp, int Tn) {
    const int t = blockIdx.x;
    if (t >= Tn) return;
    const int kseg = t / SEGA, grp = kseg / GRP;
    __shared__ float Cst[256], Id[256];
    __shared__ float NA[256], NJ[256];
    __shared__ float IpW[256], ZCt[256], fc[256];
    __shared__ float M[256], pcm[256], U[256], S2[256], bA[256], scr[256], t1[256], Z1[256];
    __shared__ float bst[16], Nb2[16], w1[16], zb[16], fmv[16], pm[16], bqv[16];
    const int tid = threadIdx.x, i = tid >> 4, j = tid & 15;
    const int lane = tid & 31, wid = tid >> 5;
    Id[tid] = (i == j) ? 1.f : 0.f;
    Cst[tid] = g_xC[grp][tid];
    if (tid < 16) bst[tid] = g_xb[grp][tid];
    __syncthreads();
    light_compose(Cst, bst, g_lA[kseg], g_lC[kseg], g_lJ[kseg], g_lb[kseg], g_le[kseg],
                  NA, NJ, IpW, ZCt, zb, Nb2, w1, Id, tid, i, j, lane, wid);
    light_compose(Cst, bst, g_pA[t], g_pC[t], g_pJ[t], g_pb[t], g_pe[t],
                  NA, NJ, IpW, ZCt, zb, Nb2, w1, Id, tid, i, j, lane, wid);
    fc[tid] = Cst[tid];
    if (tid < 16) fmv[tid] = bst[tid];
    __syncthreads();
    if (t == Tn - 1) {
        g_fcF[tid] = fc[tid];
        if (tid < 16) g_fmF[tid] = fmv[tid];
        return;  // block-uniform
    }
    const int tt = t + 1;
    NA[tid] = wq_[tid];
    NJ[tid] = wp[tid];
    ZCt[tid] = hq_[tid];
    Id[tid] = g_OmP[tid];
    if (tid < 16) bqv[tid] = qb[tid];
    __syncthreads();
    M[tid] = dot_rc(NA, fc, i, j);
    if (tid < 16) pm[tid] = mv(NA, fmv, tid) + bqv[tid];
    __syncthreads();
    pcm[tid] = dot_rt(M, NA, i, j) + qtc[tid];
    __syncthreads();
    U[tid] = dot_rc(ZCt, pcm, i, j);
    __syncthreads();
    S2[tid] = dot_rt(U, ZCt, i, j) + qec[tid];
    __syncthreads();
    if (wid == 0) {
        float ldp = warp_gj_solve(pcm, M, bA, lane);
        if (lane == 0) g_ldp[tt] = ldp;
    } else if (wid == 5) {
        float lds = warp_gj_solve(S2, U, scr, lane);
        if (lane == 0) g_lds[tt] = lds;
    }
    __syncthreads();
    t1[tid] = dot_rc(NJ, bA, i, j) - ((i == j) ? 1.f : 0.f);
    g_bcov[tt][tid] = fc[tid] - dot_rc(bA, M, i, j);
    g_P[tt][tid] = bA[tid];
    if (tid < 16) g_ba[tt][tid] = fmv[tid] - mv(bA, pm, tid);
    __syncthreads();
    Z1[tid] = dot_rc(Id, t1, i, j);
    __syncthreads();
    g_Q[tt][tid] = dot_tc(t1, Z1, i, j);
}

// ================= par: gramA ∥ scan1; last block runs fused gramB+scan2 =================
__global__ void __launch_bounds__(256, 1) k_par(int Tn, int nsegG) {
    __shared__ float P[256], Q[256], Qo[256], bAs[256], Qs[256], Em[256], nP[256], Y[256], Yo[256];
    __shared__ float Gf[256], Gof[256], Pf[256], Qpf[256], Qopf[256], Yf[256], Yof[256];
    __shared__ float Gr[256], Gn[256], Sr[256];
    __shared__ float u[16], un[16], ba[16], Gu[16], gn[16], Su[16];
    __shared__ unsigned isLast;
    const int tid = threadIdx.x, i = tid >> 4, j = tid & 15;
    const int N = Tn - 1;
    if ((int)blockIdx.x < nsegG) {
        const int k = blockIdx.x;
        const int s0 = 16 * k + 1;
        if (s0 <= N) {
            const int send = min(16 * k + 16, N);
            Em[tid] = g_Em[tid];
            P[tid] = g_P[s0][tid]; Q[tid] = g_Q[s0][tid]; Qo[tid] = Em[tid];
            __syncthreads();
            g_mP[s0][tid] = P[tid]; g_mQ[s0][tid] = Q[tid]; g_mQo[s0][tid] = Qo[tid];
            for (int s = s0 + 1; s <= send; s++) {
                bAs[tid] = g_P[s][tid]; Qs[tid] = g_Q[s][tid];
                __syncthreads();
                nP[tid] = dot_rc(P, bAs, i, j);
                Y[tid] = dot_rc(Q, bAs, i, j);
                Yo[tid] = dot_rc(Qo, bAs, i, j);
                __syncthreads();
                float q = dot_tc(bAs, Y, i, j) + Qs[tid];
                float qo = dot_tc(bAs, Yo, i, j) + Em[tid];
                P[tid] = nP[tid]; Q[tid] = q; Qo[tid] = qo;
                g_mP[s][tid] = nP[tid]; g_mQ[s][tid] = q; g_mQo[s][tid] = qo;
                __syncthreads();
            }
        }
    } else {
        const int b = blockIdx.x - nsegG;
        const int lo = b * SEG;
        if (lo < Tn) {
            int hi = min(lo + SEG, Tn);
            Gr[tid] = (i == j) ? 1.f : 0.f;  // R
            if (tid < 16) u[tid] = 0.f;
            __syncthreads();
            for (int t = hi - 1; t >= lo; t--) {
                g_Lr[t][tid] = Gr[tid];
                if (tid < 16) g_Lu[t][tid] = u[tid];
                if (t == 0) break;
                bAs[tid] = g_P[t][tid];
                if (tid < 16) ba[tid] = g_ba[t][tid];
                __syncthreads();
                Gn[tid] = dot_rc(bAs, Gr, i, j);
                if (tid < 16) un[tid] = ba[tid] + mv(bAs, u, tid);
                __syncthreads();
                Gr[tid] = Gn[tid];
                if (tid < 16) u[tid] = un[tid];
                __syncthreads();
            }
            g_Sr[b][tid] = Gr[tid];
            if (tid < 16) g_Su[b][tid] = u[tid];
        }
    }
    // last block: fused gramB + scan2 (independent serial chains interleaved)
    __threadfence();
    __syncthreads();
    if (tid == 0) isLast = (atomicAdd(&g_ctr[1], 1u) == gridDim.x - 1);
    __syncthreads();
    if (!isLast) return;
    {
        const int nsg = (N >= 1) ? ((N + 15) / 16) : 0;
        const int nseg2 = (Tn + SEG - 1) / SEG;
        const int M_ = max(nsg, nseg2);
        Gf[tid] = g_Om0[tid]; Gof[tid] = g_Em[tid];
        Gr[tid] = (i == j) ? 1.f : 0.f;
        if (tid < 16) Gu[tid] = 0.f;
        __syncthreads();
        for (int m = 0; m < M_; m++) {
            const int kk = m;               // gramB forward index
            const int bb = nseg2 - 1 - m;   // scan2 backward index
            bool doG = (kk < nsg);
            bool doS = (bb >= 0);
            if (doG) {
                g_Gx[kk][tid] = Gf[tid];
                g_Gox[kk][tid] = Gof[tid];
            }
            if (doS) {
                g_Gr[bb][tid] = Gr[tid];
                if (tid < 16) g_Gu[bb][tid] = Gu[tid];
            }
            bool stepG = doG && (kk < nsg - 1);
            bool stepS = doS && (bb > 0);
            if (stepG) {
                const int send = min(16 * kk + 16, N);
                Pf[tid] = g_mP[send][tid];
                Qpf[tid] = g_mQ[send][tid];
                Qopf[tid] = g_mQo[send][tid];
            }
            if (stepS) {
                Sr[tid] = g_Sr[bb][tid];
                if (tid < 16) Su[tid] = g_Su[bb][tid];
            }
            __syncthreads();
            if (stepG) {
                Yf[tid] = dot_rc(Gf, Pf, i, j);
                Yof[tid] = dot_rc(Gof, Pf, i, j);
            }
            if (stepS) {
                Gn[tid] = dot_rc(Sr, Gr, i, j);
                if (tid < 16) gn[tid] = mv(Sr, Gu, tid) + Su[tid];
            }
            __syncthreads();
            if (stepG) {
                Gf[tid] = dot_tc(Pf, Yf, i, j) + Qpf[tid];
                Gof[tid] = dot_tc(Pf, Yof, i, j) + Qopf[tid];
            }
            if (stepS) {
                Gr[tid] = Gn[tid];
                if (tid < 16) Gu[tid] = gn[tid];
            }
            __syncthreads();
        }
    }
}

// ================= tail (+ last block finalizes) =================
__global__ void __launch_bounds__(256, 1) k_tail(
    const float* obs, const float* wp, const float* pb_, const float* wep,
    const float* peb, const float* ppm_, float* out, int Tn) {
    const int t = blockIdx.x;
    __shared__ float OmP[256], omm[256], Om0[256], Wp[256], Wep[256], fc[256], Gr[256];
    __shared__ float Lr[256], bA[256], Rf[256], Ai[256], A[256], Ao[256], AF[256], AoF[256];
    __shared__ float G[256], Go[256], P[256], Y[256], Yo[256], Fm[256];
    __shared__ float fm[16], Gu[16], Lu[16], bav[16], uf[16], Bv[16], Bo[16];
    __shared__ float cv[16], co[16], y[16], bp[16], ebp[16], ppm[16];
    __shared__ double dred[8], r0[8], r1[8], r2[8];
    __shared__ unsigned isLast;
    const int tid = threadIdx.x, i = tid >> 4, j = tid & 15;
    const int lane = tid & 31, wid = tid >> 5;

    OmP[tid] = g_OmP[tid]; omm[tid] = g_om[tid]; Om0[tid] = g_Om0[tid];
    Wp[tid] = wp[tid]; Wep[tid] = wep[tid]; Fm[tid] = g_Fm[tid];
    fc[tid] = g_fcF[tid]; Gr[tid] = g_Gr[t / SEG][tid];
    Lr[tid] = g_Lr[t][tid];
    bA[tid] = (t > 0) ? g_P[t][tid] : 0.f;
    if (tid < 16) {
        fm[tid] = g_fmF[tid]; Gu[tid] = g_Gu[t / SEG][tid];
        bp[tid] = pb_[tid]; ebp[tid] = peb[tid]; ppm[tid] = ppm_[tid];
        Lu[tid] = g_Lu[t][tid];
        bav[tid] = (t > 0) ? g_ba[t][tid] : 0.f;
        y[tid] = obs[t * 16 + tid];
    }
    __syncthreads();

    double acc = 0.0;
    if (t >= 1) {
        const int s = t - 1;
        if (s == 0) {
            G[tid] = Om0[tid]; Go[tid] = g_Em[tid];
            __syncthreads();
        } else {
            const int k = (s - 1) >> 4;
            G[tid] = g_Gx[k][tid]; Go[tid] = g_Gox[k][tid];
            P[tid] = g_mP[s][tid];
            __syncthreads();
            Y[tid] = dot_rc(G, P, i, j);
            Yo[tid] = dot_rc(Go, P, i, j);
            __syncthreads();
            G[tid] = dot_tc(P, Y, i, j) + g_mQ[s][tid];
            Go[tid] = dot_tc(P, Yo, i, j) + g_mQo[s][tid];
            __syncthreads();
        }
        acc += (double)((G[tid] + Go[tid] - 0.5f * Fm[tid]) * g_bcov[t][tid]);
    }
    Rf[tid] = dot_rc(Lr, Gr, i, j);
    Ai[tid] = (t > 0) ? (dot_rc(Wp, bA, i, j) - ((i == j) ? 1.f : 0.f))
                      : ((i == j) ? 1.f : 0.f);
    if (tid < 16) {
        uf[tid] = mv(Lr, Gu, tid) + Lu[tid];
        Bv[tid] = (t > 0) ? (mv(Wp, bav, tid) + bp[tid]) : (-ppm[tid]);
    }
    __syncthreads();
    A[tid] = dot_rc(Ai, Rf, i, j);
    Ao[tid] = dot_rc(Wep, Rf, i, j);
    if (tid < 16) {
        Bv[tid] += mv(Ai, uf, tid);
        Bo[tid] = ebp[tid] - y[tid] + mv(Wep, uf, tid);
    }
    __syncthreads();
    AF[tid] = dot_rc(A, fc, i, j);
    AoF[tid] = dot_rc(Ao, fc, i, j);
    if (tid < 16) {
        cv[tid] = mv(A, fm, tid) + Bv[tid];
        co[tid] = mv(Ao, fm, tid) + Bo[tid];
    }
    __syncthreads();
    {
        const float* Om = (t == 0) ? Om0 : OmP;
        acc += (double)(Om[tid] * (dot_rc(AF, A, i, j) + cv[i] * cv[j])
                      + omm[tid] * (dot_rc(AoF, Ao, i, j) + co[i] * co[j]));
    }
    double v = acc;
#pragma unroll
    for (int o = 16; o; o >>= 1) v += __shfl_xor_sync(0xffffffffu, v, o);
    if (lane == 0) dred[wid] = v;
    __syncthreads();
    if (tid == 0) {
        double tot = 0.0;
#pragma unroll
        for (int w = 0; w < 8; w++) tot += dred[w];
        g_accT[t] = tot;
    }
    // last block: finalize
    __threadfence();
    __syncthreads();
    if (tid == 0) isLast = (atomicAdd(&g_ctr[2], 1u) == gridDim.x - 1);
    __syncthreads();
    if (!isLast) return;
    {
        const int N = Tn - 1;
        double a = 0.0, b = 0.0, c = 0.0;
        for (int tt = tid; tt < Tn; tt += 256) {
            if (tt >= 1) { a += (double)g_ldp[tt]; b += (double)g_lds[tt]; }
            c += g_accT[tt];
        }
#pragma unroll
        for (int o = 16; o; o >>= 1) {
            a += __shfl_xor_sync(0xffffffffu, a, o);
            b += __shfl_xor_sync(0xffffffffu, b, o);
            c += __shfl_xor_sync(0xffffffffu, c, o);
        }
        if (lane == 0) { r0[wid] = a; r1[wid] = b; r2[wid] = c; }
        __syncthreads();
        if (tid == 0) {
            double SP = 0.0, sumS = 0.0, accs = 0.0;
#pragma unroll
            for (int w = 0; w < 8; w++) { SP += r0[w]; sumS += r1[w]; accs += r2[w]; }
            double ldpN = (N >= 1) ? (double)g_ldp[N] : 0.0;
            double ldsN = (N >= 1) ? (double)g_lds[N] : 0.0;
            double set_acc = g_sc[0], K0d = g_sc[1], ldfc0 = g_sc[2];
            double LDSqd = g_sc[3], LDRqd = g_sc[4];
            double Nd = (double)N;
            double sumF = ldfc0 + (SP - ldpN) + (Nd - 1.0) * LDRqd - (sumS - ldsN);
            double FN = (N >= 1) ? (ldpN + LDRqd - ldsN) : ldfc0;
            double tot = set_acc + Nd * (K0d + 0.5 * LDSqd) - 0.5 * SP + 0.5 * sumF
                       + 0.5 * (16.0 * LOG2PI + FN) + 8.0 + accs;
            out[0] = (float)tot;
        }
    }
}

extern "C" void kernel_launch(void* const* d_in, const int* in_sizes, int n_in,
                              void* d_out, int out_size) {
    int Tn = in_sizes[0] / 16;
    if (Tn > TMAX) Tn = TMAX;
    const float* obs = (const float*)d_in[0];
    const float* ppm_ = (const float*)d_in[1];
    const float* ppc = (const float*)d_in[2];
    const float* wp = (const float*)d_in[3];
    const float* pb_ = (const float*)d_in[4];
    const float* ptc = (const float*)d_in[5];
    const float* wep = (const float*)d_in[6];
    const float* peb = (const float*)d_in[7];
    const float* pec = (const float*)d_in[8];
    const float* qpm = (const float*)d_in[9];
    const float* qpc = (const float*)d_in[10];
    const float* wq_ = (const float*)d_in[11];
    const float* qb = (const float*)d_in[12];
    const float* qtc = (const float*)d_in[13];
    const float* hq_ = (const float*)d_in[14];
    const float* qeb = (const float*)d_in[15];
    const float* qec = (const float*)d_in[16];
    const int nsegA = (Tn + SEGA - 1) / SEGA;
    const int ngrp = (nsegA + GRP - 1) / GRP;
    const int nsegG = (Tn + 15) / 16;
    const int nseg1 = (Tn + SEG - 1) / SEG;
    k_setup<<<1, 256>>>(obs, ppm_, ppc, wp, pb_, ptc, wep, peb, pec, qpm, qpc,
                        wq_, qb, qtc, hq_, qeb, qec, Tn);
    k_elemA<<<nsegA, 256>>>(obs, Tn);
    k_elemB<<<ngrp, 256>>>(Tn);
    k_elemCD<<<Tn, 256>>>(wq_, qtc, hq_, qec, qb, wp, Tn);
    k_par<<<nsegG + nseg1, 256>>>(Tn, nsegG);
    k_tail<<<Tn, 256>>>(obs, wp, pb_, wep, peb, ppm_, (float*)d_out, Tn);
}